// round 2
// baseline (speedup 1.0000x reference)
#include <cuda_runtime.h>
#include <cuda_bf16.h>
#include <cstdint>

// ---------------- problem constants ----------------
#define BB     4
#define CC     64
#define H0     48
#define W0     48
#define QQ     16384
#define NSHIFT 4
#define MROWS  (BB*QQ*NSHIFT)   // 262144
#define INDIM  260
#define HID    256

// ---------------- scratch ( __device__ globals: allocation-free ) -------------
__device__ float g_feat [BB*CC*H0*W0];          // 48x48
__device__ float g_feat1[BB*CC*96*96];
__device__ float g_feat2[BB*CC*192*192];
__device__ float g_feat3[BB*CC*384*384];
__device__ float g_feat4[BB*CC*192*192];
__device__ float g_feat5[BB*CC*96*96];
__device__ float g_X    [(size_t)MROWS*INDIM];
__device__ float g_H0b  [(size_t)MROWS*HID];
__device__ float g_H1b  [(size_t)MROWS*HID];
__device__ float g_P    [(size_t)MROWS*3];
__device__ float g_area [MROWS];

// ---------------- enc conv 3->64, 3x3 pad1 ----------------
__global__ void enc_conv(const float* __restrict__ inp,
                         const float* __restrict__ w,
                         const float* __restrict__ b)
{
    int idx = blockIdx.x*256 + threadIdx.x;
    if (idx >= BB*CC*H0*W0) return;
    int x  = idx % W0;
    int y  = (idx / W0) % H0;
    int co = (idx / (H0*W0)) % CC;
    int bb = idx / (H0*W0*CC);
    float acc = b[co];
    const float* ib = inp + (size_t)bb*3*H0*W0;
    #pragma unroll
    for (int ci = 0; ci < 3; ci++) {
        #pragma unroll
        for (int ky = 0; ky < 3; ky++) {
            int yy = y + ky - 1;
            if (yy < 0 || yy >= H0) continue;
            #pragma unroll
            for (int kx = 0; kx < 3; kx++) {
                int xx = x + kx - 1;
                if (xx < 0 || xx >= W0) continue;
                acc += ib[ci*H0*W0 + yy*W0 + xx] * w[(co*3 + ci)*9 + ky*3 + kx];
            }
        }
    }
    g_feat[idx] = acc;
}

// ---------------- conv3x3 64->256 + pixel shuffle (fused) ----------------
// grid (W/16, H/16, B*64), block (16,16). cog = output channel after shuffle.
__global__ void up_conv_ps(const float* __restrict__ in, float* __restrict__ out,
                           int H, int W,
                           const float* __restrict__ w, const float* __restrict__ bias)
{
    __shared__ float s_in[8][18][18];
    __shared__ float s_w[4][8][9];
    int tx = threadIdx.x, ty = threadIdx.y, tid = ty*16 + tx;
    int x0 = blockIdx.x*16, y0 = blockIdx.y*16;
    int bb = blockIdx.z >> 6;
    int cog = blockIdx.z & 63;
    float acc[4] = {0.f,0.f,0.f,0.f};
    const float* inb = in + (size_t)bb*CC*H*W;

    for (int c0 = 0; c0 < CC; c0 += 8) {
        for (int i = tid; i < 8*18*18; i += 256) {
            int ci = i / 324, rem = i % 324, r = rem / 18, c = rem % 18;
            int y = y0 + r - 1, x = x0 + c - 1;
            float v = 0.f;
            if (y >= 0 && y < H && x >= 0 && x < W)
                v = inb[(size_t)(c0+ci)*H*W + y*W + x];
            s_in[ci][r][c] = v;
        }
        for (int i = tid; i < 288; i += 256) {
            int col = i / 72, rem = i % 72, ci = rem / 9, k = rem % 9;
            s_w[col][ci][k] = w[((size_t)(cog*4+col)*CC + c0+ci)*9 + k];
        }
        __syncthreads();
        #pragma unroll
        for (int ci = 0; ci < 8; ci++) {
            float v[9];
            #pragma unroll
            for (int j = 0; j < 9; j++) v[j] = s_in[ci][ty + j/3][tx + j%3];
            #pragma unroll
            for (int col = 0; col < 4; col++) {
                float a = acc[col];
                #pragma unroll
                for (int k = 0; k < 9; k++) a += v[k]*s_w[col][ci][k];
                acc[col] = a;
            }
        }
        __syncthreads();
    }
    int H2 = 2*H, W2 = 2*W;
    float* ob = out + ((size_t)bb*CC + cog)*H2*W2;
    int oy = y0 + ty, ox = x0 + tx;
    #pragma unroll
    for (int col = 0; col < 4; col++) {
        int r = col >> 1, s = col & 1;
        ob[(size_t)(2*oy + r)*W2 + 2*ox + s] = acc[col] + bias[cog*4 + col];
    }
}

// ---------------- stride2 conv3x3 + 1x1 skip (fused) ----------------
// grid (OW/16, OH/16, B*16), block (16,16). 4 c_out per thread.
__global__ void down_fused(const float* __restrict__ in3, const float* __restrict__ skin,
                           float* __restrict__ out, int OH, int OW,
                           const float* __restrict__ dw, const float* __restrict__ db,
                           const float* __restrict__ sw, const float* __restrict__ sb)
{
    __shared__ float s_in[8][33][33];
    __shared__ float s_w[4][8][9];
    __shared__ float s_sw[4][8];
    int IH = 2*OH, IW = 2*OW;
    int tx = threadIdx.x, ty = threadIdx.y, tid = ty*16 + tx;
    int x0 = blockIdx.x*16, y0 = blockIdx.y*16;
    int bb = blockIdx.z >> 4;
    int cog = blockIdx.z & 15;
    float acc[4] = {0.f,0.f,0.f,0.f};
    const float* inb = in3 + (size_t)bb*CC*IH*IW;
    const float* skb = skin + (size_t)bb*CC*OH*OW;
    int oy = y0 + ty, ox = x0 + tx;

    for (int c0 = 0; c0 < CC; c0 += 8) {
        for (int i = tid; i < 8*33*33; i += 256) {
            int ci = i / 1089, rem = i % 1089, r = rem / 33, c = rem % 33;
            int y = 2*y0 - 1 + r, x = 2*x0 - 1 + c;
            float v = 0.f;
            if (y >= 0 && y < IH && x >= 0 && x < IW)
                v = inb[(size_t)(c0+ci)*IH*IW + y*IW + x];
            s_in[ci][r][c] = v;
        }
        for (int i = tid; i < 288; i += 256) {
            int col = i / 72, rem = i % 72, ci = rem / 9, k = rem % 9;
            s_w[col][ci][k] = dw[((size_t)(cog*4+col)*CC + c0+ci)*9 + k];
        }
        if (tid < 32) {
            int col = tid >> 3, ci = tid & 7;
            s_sw[col][ci] = sw[(cog*4+col)*CC + c0+ci];
        }
        __syncthreads();
        #pragma unroll
        for (int ci = 0; ci < 8; ci++) {
            float v[9];
            #pragma unroll
            for (int j = 0; j < 9; j++) v[j] = s_in[ci][2*ty + j/3][2*tx + j%3];
            float sv = skb[(size_t)(c0+ci)*OH*OW + oy*OW + ox];
            #pragma unroll
            for (int col = 0; col < 4; col++) {
                float a = acc[col];
                #pragma unroll
                for (int k = 0; k < 9; k++) a += v[k]*s_w[col][ci][k];
                a += sv * s_sw[col][ci];
                acc[col] = a;
            }
        }
        __syncthreads();
    }
    float* ob = out + (size_t)bb*CC*OH*OW;
    #pragma unroll
    for (int col = 0; col < 4; col++) {
        int co = cog*4 + col;
        ob[(size_t)co*OH*OW + oy*OW + ox] = acc[col] + db[co] + sb[co];
    }
}

// ---------------- gather + build X rows ----------------
__device__ __forceinline__ int nidx(float cc, float n)
{
    float f = rintf((cc + 1.0f)*(n*0.5f) - 0.5f);   // round-half-even matches jnp.round
    f = fminf(fmaxf(f, 0.0f), n - 1.0f);
    return (int)f;
}

__global__ void gather_build(const float* __restrict__ coord, const float* __restrict__ cell)
{
    int tid = threadIdx.x;
    int row = blockIdx.x*4 + (tid >> 6);
    int c   = tid & 63;
    int s   = row & 3;
    int bq  = row >> 2;               // b*Q + q
    int b   = bq >> 14;               // Q = 16384
    float cy = coord[(size_t)bq*2 + 0];
    float cx = coord[(size_t)bq*2 + 1];
    float vx = (s & 2) ? 1.f : -1.f;
    float vy = (s & 1) ? 1.f : -1.f;
    const float RX = 1.0f/48.0f;
    float sy = fminf(fmaxf(cy + vx*RX + 1e-6f, -1.f + 1e-6f), 1.f - 1e-6f);
    float sx = fminf(fmaxf(cx + vy*RX + 1e-6f, -1.f + 1e-6f), 1.f - 1e-6f);
    int iy0 = nidx(sy, 48.f),  ix0 = nidx(sx, 48.f);
    int iy1 = nidx(sy, 96.f),  ix1 = nidx(sx, 96.f);
    int iy2 = nidx(sy, 192.f), ix2 = nidx(sx, 192.f);
    int iy3 = nidx(sy, 384.f), ix3 = nidx(sx, 384.f);

    float* xr = g_X + (size_t)row*INDIM;
    xr[c]       = g_feat [((size_t)(b*CC + c)*48  + iy0)*48  + ix0];
    xr[64 + c]  = g_feat5[((size_t)(b*CC + c)*96  + iy1)*96  + ix1];
    xr[128 + c] = g_feat4[((size_t)(b*CC + c)*192 + iy2)*192 + ix2];
    xr[192 + c] = g_feat3[((size_t)(b*CC + c)*384 + iy3)*384 + ix3];
    if (c == 0) {
        float qcy = -1.f + (2.f*iy0 + 1.f)/48.f;
        float qcx = -1.f + (2.f*ix0 + 1.f)/48.f;
        float ry_ = (cy - qcy)*48.f;
        float rx_ = (cx - qcx)*48.f;
        xr[256] = ry_;
        xr[257] = rx_;
        xr[258] = cell[(size_t)bq*2 + 0]*48.f;
        xr[259] = cell[(size_t)bq*2 + 1]*48.f;
        g_area[row] = fabsf(ry_*rx_) + 1e-9f;
    }
}

// ---------------- SGEMM: C = relu?(A[M,K] @ W[K,N] + bias) ; BM=BN=64, BK=8 ----------------
__global__ void __launch_bounds__(128)
gemm_bias_relu(const float* __restrict__ A, const float* __restrict__ Bw,
               const float* __restrict__ bias, float* __restrict__ C,
               int M, int N, int K, int relu)
{
    __shared__ float As[8][64];
    __shared__ float Bs[8][64];
    int tid = threadIdx.x;
    int m0 = blockIdx.y*64, n0 = blockIdx.x*64;
    int ty = tid >> 4, tx = tid & 15;
    int msub = ty*8, nsub = tx*4;
    int la_m = tid >> 1, la_k = (tid & 1)*4;
    int lb_k = tid >> 4, lb_n = (tid & 15)*4;
    float acc[8][4];
    #pragma unroll
    for (int i = 0; i < 8; i++)
        #pragma unroll
        for (int j = 0; j < 4; j++) acc[i][j] = 0.f;

    for (int k0 = 0; k0 < K; k0 += 8) {
        // load A (transpose into smem)
        const float* ap = A + (size_t)(m0 + la_m)*K + k0 + la_k;
        float4 av;
        if (k0 + la_k + 3 < K) {
            av = *(const float4*)ap;
        } else {
            av.x = (k0 + la_k + 0 < K) ? ap[0] : 0.f;
            av.y = (k0 + la_k + 1 < K) ? ap[1] : 0.f;
            av.z = (k0 + la_k + 2 < K) ? ap[2] : 0.f;
            av.w = (k0 + la_k + 3 < K) ? ap[3] : 0.f;
        }
        As[la_k + 0][la_m] = av.x;
        As[la_k + 1][la_m] = av.y;
        As[la_k + 2][la_m] = av.z;
        As[la_k + 3][la_m] = av.w;
        // load B
        float4 bv = make_float4(0.f,0.f,0.f,0.f);
        if (k0 + lb_k < K)
            bv = *(const float4*)(Bw + (size_t)(k0 + lb_k)*N + n0 + lb_n);
        *(float4*)&Bs[lb_k][lb_n] = bv;
        __syncthreads();
        #pragma unroll
        for (int kk = 0; kk < 8; kk++) {
            float a[8], bb4[4];
            *(float4*)(a)   = *(const float4*)&As[kk][msub];
            *(float4*)(a+4) = *(const float4*)&As[kk][msub+4];
            *(float4*)(bb4) = *(const float4*)&Bs[kk][nsub];
            #pragma unroll
            for (int i = 0; i < 8; i++)
                #pragma unroll
                for (int j = 0; j < 4; j++)
                    acc[i][j] += a[i]*bb4[j];
        }
        __syncthreads();
    }
    #pragma unroll
    for (int i = 0; i < 8; i++) {
        int m = m0 + msub + i;
        #pragma unroll
        for (int j = 0; j < 4; j++) {
            int n = n0 + nsub + j;
            float v = acc[i][j] + bias[n];
            if (relu) v = fmaxf(v, 0.f);
            C[(size_t)m*N + n] = v;
        }
    }
}

// ---------------- last layer: [M,256] @ [256,3] + b ----------------
__global__ void mlp_last(const float* __restrict__ Hin, const float* __restrict__ W4,
                         const float* __restrict__ b4)
{
    int warp = threadIdx.x >> 5, lane = threadIdx.x & 31;
    int row = blockIdx.x*4 + warp;
    const float* hr = Hin + (size_t)row*HID;
    float a0 = 0.f, a1 = 0.f, a2 = 0.f;
    for (int k = lane; k < HID; k += 32) {
        float h = hr[k];
        a0 += h*W4[k*3 + 0];
        a1 += h*W4[k*3 + 1];
        a2 += h*W4[k*3 + 2];
    }
    #pragma unroll
    for (int o = 16; o; o >>= 1) {
        a0 += __shfl_down_sync(0xffffffffu, a0, o);
        a1 += __shfl_down_sync(0xffffffffu, a1, o);
        a2 += __shfl_down_sync(0xffffffffu, a2, o);
    }
    if (lane == 0) {
        g_P[(size_t)row*3 + 0] = a0 + b4[0];
        g_P[(size_t)row*3 + 1] = a1 + b4[1];
        g_P[(size_t)row*3 + 2] = a2 + b4[2];
    }
}

// ---------------- ensemble + bilinear border skip ----------------
__global__ void ensemble(const float* __restrict__ coord, const float* __restrict__ inp,
                         float* __restrict__ out)
{
    int bq = blockIdx.x*256 + threadIdx.x;
    if (bq >= BB*QQ) return;
    int b = bq >> 14;
    float cy = coord[(size_t)bq*2 + 0];
    float cx = coord[(size_t)bq*2 + 1];
    int base = bq*4;
    float a0 = g_area[base+0], a1 = g_area[base+1], a2 = g_area[base+2], a3 = g_area[base+3];
    float inv = 1.0f/(a0 + a1 + a2 + a3);
    float w0 = a3*inv, w1 = a2*inv, w2 = a1*inv, w3 = a0*inv;   // diagonal swap
    float r[3];
    #pragma unroll
    for (int c = 0; c < 3; c++) {
        r[c] = g_P[(size_t)(base+0)*3 + c]*w0
             + g_P[(size_t)(base+1)*3 + c]*w1
             + g_P[(size_t)(base+2)*3 + c]*w2
             + g_P[(size_t)(base+3)*3 + c]*w3;
    }
    // bilinear border sample of inp at original coord
    float fy = fminf(fmaxf((cy + 1.f)*24.f - 0.5f, 0.f), 47.f);
    float fx = fminf(fmaxf((cx + 1.f)*24.f - 0.5f, 0.f), 47.f);
    float y0f = floorf(fy), x0f = floorf(fx);
    int y0 = (int)y0f, x0 = (int)x0f;
    float wy = fy - y0f, wx = fx - x0f;
    int y1 = min(y0 + 1, 47), x1 = min(x0 + 1, 47);
    const float* ib = inp + (size_t)b*3*H0*W0;
    #pragma unroll
    for (int ch = 0; ch < 3; ch++) {
        const float* p = ib + ch*H0*W0;
        float v00 = p[y0*48 + x0], v01 = p[y0*48 + x1];
        float v10 = p[y1*48 + x0], v11 = p[y1*48 + x1];
        r[ch] += v00*(1.f - wy)*(1.f - wx) + v01*(1.f - wy)*wx
               + v10*wy*(1.f - wx) + v11*wy*wx;
        out[(size_t)bq*3 + ch] = r[ch];
    }
}

// ---------------- host launch ----------------
static float* dev_ptr(float* sym) { return sym; } // (unused helper)

extern "C" void kernel_launch(void* const* d_in, const int* in_sizes, int n_in,
                              void* d_out, int out_size)
{
    const float* inp     = (const float*)d_in[0];
    const float* coord   = (const float*)d_in[1];
    const float* cell    = (const float*)d_in[2];
    const float* enc_w   = (const float*)d_in[3];
    const float* enc_b   = (const float*)d_in[4];
    const float* up1_w   = (const float*)d_in[5];
    const float* up1_b   = (const float*)d_in[6];
    const float* up2_w   = (const float*)d_in[7];
    const float* up2_b   = (const float*)d_in[8];
    const float* up3_w   = (const float*)d_in[9];
    const float* up3_b   = (const float*)d_in[10];
    const float* skip1_w = (const float*)d_in[11];
    const float* skip1_b = (const float*)d_in[12];
    const float* skip2_w = (const float*)d_in[13];
    const float* skip2_b = (const float*)d_in[14];
    const float* down4_w = (const float*)d_in[15];
    const float* down4_b = (const float*)d_in[16];
    const float* down5_w = (const float*)d_in[17];
    const float* down5_b = (const float*)d_in[18];
    const float* mlp_w0  = (const float*)d_in[19];
    const float* mlp_b0  = (const float*)d_in[20];
    const float* mlp_w1  = (const float*)d_in[21];
    const float* mlp_b1  = (const float*)d_in[22];
    const float* mlp_w2  = (const float*)d_in[23];
    const float* mlp_b2  = (const float*)d_in[24];
    const float* mlp_w3  = (const float*)d_in[25];
    const float* mlp_b3  = (const float*)d_in[26];
    const float* mlp_w4  = (const float*)d_in[27];
    const float* mlp_b4  = (const float*)d_in[28];
    float* out = (float*)d_out;

    float *p_feat, *p_feat1, *p_feat2, *p_feat3, *p_feat4, *p_feat5;
    float *p_X, *p_H0, *p_H1;
    cudaGetSymbolAddress((void**)&p_feat,  g_feat);
    cudaGetSymbolAddress((void**)&p_feat1, g_feat1);
    cudaGetSymbolAddress((void**)&p_feat2, g_feat2);
    cudaGetSymbolAddress((void**)&p_feat3, g_feat3);
    cudaGetSymbolAddress((void**)&p_feat4, g_feat4);
    cudaGetSymbolAddress((void**)&p_feat5, g_feat5);
    cudaGetSymbolAddress((void**)&p_X,  g_X);
    cudaGetSymbolAddress((void**)&p_H0, g_H0b);
    cudaGetSymbolAddress((void**)&p_H1, g_H1b);

    // 1. encoder conv
    {
        int total = BB*CC*H0*W0;
        enc_conv<<<(total + 255)/256, 256>>>(inp, enc_w, enc_b);
    }
    // 2-4. up convs + pixel shuffle
    {
        dim3 blk(16,16);
        up_conv_ps<<<dim3(48/16,  48/16,  BB*64), blk>>>(p_feat,  p_feat1, 48, 48,  up1_w, up1_b);
        up_conv_ps<<<dim3(96/16,  96/16,  BB*64), blk>>>(p_feat1, p_feat2, 96, 96,  up2_w, up2_b);
        up_conv_ps<<<dim3(192/16, 192/16, BB*64), blk>>>(p_feat2, p_feat3, 192,192, up3_w, up3_b);
    }
    // 5-6. strided down convs + 1x1 skips
    {
        dim3 blk(16,16);
        down_fused<<<dim3(192/16, 192/16, BB*16), blk>>>(p_feat3, p_feat2, p_feat4, 192, 192,
                                                         down4_w, down4_b, skip1_w, skip1_b);
        down_fused<<<dim3(96/16,  96/16,  BB*16), blk>>>(p_feat4, p_feat1, p_feat5, 96, 96,
                                                         down5_w, down5_b, skip2_w, skip2_b);
    }
    // 7. gather + build X
    gather_build<<<MROWS/4, 256>>>(coord, cell);

    // 8-11. MLP hidden layers
    {
        dim3 grid(HID/64, MROWS/64);
        gemm_bias_relu<<<grid, 128>>>(p_X,  mlp_w0, mlp_b0, p_H0, MROWS, HID, INDIM, 1);
        gemm_bias_relu<<<grid, 128>>>(p_H0, mlp_w1, mlp_b1, p_H1, MROWS, HID, HID,   1);
        gemm_bias_relu<<<grid, 128>>>(p_H1, mlp_w2, mlp_b2, p_H0, MROWS, HID, HID,   1);
        gemm_bias_relu<<<grid, 128>>>(p_H0, mlp_w3, mlp_b3, p_H1, MROWS, HID, HID,   1);
    }
    // 12. last layer
    mlp_last<<<MROWS/4, 128>>>(p_H1, mlp_w4, mlp_b4);

    // 13. ensemble + bilinear skip
    ensemble<<<(BB*QQ + 255)/256, 256>>>(coord, inp, out);
}